// round 7
// baseline (speedup 1.0000x reference)
#include <cuda_runtime.h>
#include <cuda_bf16.h>
#include <cstdint>

// Problem constants (fixed by the dataset instance)
#define NROWS  4096
#define DDIM   1024
#define NCLS   512
#define NNEGS  3679
#define HHALF  7534592u        // n/2 for threefry lane pairing, n = 4096*3679
#define MARGINF 0.15f
#define TTILES 32              // 4096 / 128

// dynamic smem layout for loss kernel (bytes)
#define SM_ASM   0
#define SM_BSM   20480
#define SM_DP    40960
#define SM_TOTAL 50176         // + Dp 256*9*4 = 9216

// Scratch (static __device__ arrays: allocation-free)
__device__ float g_xn[NROWS * DDIM];            // normalized samples, fp32 (posdist)
__device__ __nv_bfloat16 g_xb[NROWS * DDIM];    // normalized samples, bf16 (gram)
__device__ float g_dpos[NROWS * 8];             // per-row positive distances
__device__ unsigned char g_rsel[NNEGS * NROWS]; // resample idx, t-major [t][i]

// ---------------------------------------------------------------------------
// Threefry-2x32-20, key (0, 42), exact JAX semantics; returns both words.
// ---------------------------------------------------------------------------
__device__ __forceinline__ void tf_block(unsigned lane, unsigned& o0, unsigned& o1) {
    const unsigned ks1 = 42u;
    const unsigned ks2 = 0x1BD11BDAu ^ 42u;
    unsigned x0 = lane;
    unsigned x1 = lane + HHALF + ks1;
#define TFR(r) { x0 += x1; x1 = (x1 << (r)) | (x1 >> (32 - (r))); x1 ^= x0; }
    TFR(13) TFR(15) TFR(26) TFR(6)   x0 += ks1; x1 += ks2 + 1u;
    TFR(17) TFR(29) TFR(16) TFR(24)  x0 += ks2; x1 += 0u  + 2u;
    TFR(13) TFR(15) TFR(26) TFR(6)   x0 += 0u;  x1 += ks1 + 3u;
    TFR(17) TFR(29) TFR(16) TFR(24)  x0 += ks1; x1 += ks2 + 4u;
    TFR(13) TFR(15) TFR(26) TFR(6)   x0 += ks2; x1 += 0u  + 5u;
#undef TFR
    o0 = x0; o1 = x1;
}

__device__ __forceinline__ float bits_to_u(unsigned bits) {
    return __uint_as_float((bits >> 9) | 0x3F800000u) - 1.0f;
}

__device__ __forceinline__ void cp16(void* s, const void* g) {
    unsigned sa = (unsigned)__cvta_generic_to_shared(s);
    asm volatile("cp.async.cg.shared.global [%0], [%1], 16;\n" :: "r"(sa), "l"(g));
}

// ---------------------------------------------------------------------------
// Kernel 1: row L2-normalize; writes fp32 and bf16 copies. Also zeroes out.
// ---------------------------------------------------------------------------
__global__ void normalize_kernel(const float* __restrict__ x,
                                 float* __restrict__ out, int out_size) {
    int row = blockIdx.x;
    int t = threadIdx.x;
    if (row == 0 && t == 0)
        for (int i = 0; i < out_size; i++) out[i] = 0.0f;
    const float4* xin = (const float4*)(x + (size_t)row * DDIM);
    float4 v = xin[t];
    float ss = v.x * v.x + v.y * v.y + v.z * v.z + v.w * v.w;
    #pragma unroll
    for (int o = 16; o; o >>= 1) ss += __shfl_down_sync(0xffffffffu, ss, o);
    __shared__ float ws[8];
    if ((t & 31) == 0) ws[t >> 5] = ss;
    __syncthreads();
    if (t < 8) {
        float s2 = ws[t];
        #pragma unroll
        for (int o = 4; o; o >>= 1) s2 += __shfl_down_sync(0xffu, s2, o);
        if (t == 0) ws[0] = s2;
    }
    __syncthreads();
    float scale = 1.0f / fmaxf(sqrtf(ws[0]), 1e-8f);
    v.x *= scale; v.y *= scale; v.z *= scale; v.w *= scale;
    ((float4*)(g_xn + (size_t)row * DDIM))[t] = v;
    __nv_bfloat16 b[4];
    b[0] = __float2bfloat16(v.x); b[1] = __float2bfloat16(v.y);
    b[2] = __float2bfloat16(v.z); b[3] = __float2bfloat16(v.w);
    *(uint2*)(g_xb + (size_t)row * DDIM + t * 4) = *(uint2*)b;
}

// ---------------------------------------------------------------------------
// Kernel 2: positive distances within each class (fp32, exact).
// ---------------------------------------------------------------------------
__global__ void posdist_kernel() {
    int cls = blockIdx.x;
    __shared__ float sm[8][DDIM];
    int t = threadIdx.x;
    const float4* src = (const float4*)(g_xn + (size_t)cls * 8 * DDIM);
    float4* dst = (float4*)(&sm[0][0]);
    #pragma unroll
    for (int idx = t; idx < 8 * DDIM / 4; idx += 256) dst[idx] = src[idx];
    __syncthreads();
    int w = t >> 5, lane = t & 31;
    for (int q = w; q < 28; q += 8) {
        int a = 0, rem = q;
        while (rem >= 7 - a) { rem -= 7 - a; a++; }
        int b = a + 1 + rem;
        float s = 0.f;
        for (int e = lane; e < DDIM; e += 32) s += sm[a][e] * sm[b][e];
        #pragma unroll
        for (int o = 16; o; o >>= 1) s += __shfl_down_sync(0xffffffffu, s, o);
        if (lane == 0) g_dpos[(cls * 8 + a) * 8 + (b - a - 1)] = 1.0f - s;
    }
}

// ---------------------------------------------------------------------------
// Kernel 3: RNG table. Thread g = t*2048 + i_low; one threefry block gives
// u for rows i_low and i_low+2048 at the same t. t-major coalesced stores.
// ---------------------------------------------------------------------------
__global__ __launch_bounds__(256) void rng_kernel() {
    unsigned g = blockIdx.x * 256u + threadIdx.x;    // g < 3679*2048
    unsigned t = g >> 11;
    unsigned i_low = g & 2047u;
    unsigned f = i_low * NNEGS + t;                  // f < HHALF
    unsigned x0, x1;
    tf_block(f, x0, x1);
    int pi = 7 - (int)(i_low & 7u);                  // same for i_low+2048
    float pf = (float)pi;
    int r0 = min((int)(bits_to_u(x0) * pf), pi - 1);
    int r1 = min((int)(bits_to_u(x1) * pf), pi - 1);
    g_rsel[t * NROWS + i_low] = (unsigned char)r0;
    g_rsel[t * NROWS + i_low + 2048] = (unsigned char)r1;
}

// ---------------------------------------------------------------------------
// Kernel 4: bf16 mma.sync Gram (triangular 1D grid, 528 CTAs; off-diagonal
// tiles first), cp.async double-buffered mainloop + table-driven epilogue.
// CTA = 128x128 tile, 8 warps, each warp 64x32 via m16n8k16 mma.sync.
// ---------------------------------------------------------------------------
__global__ __launch_bounds__(256, 2) void loss_kernel(float* __restrict__ out) {
    // decode blockIdx.x -> (by, bx), bx >= by; off-diagonal pairs first
    int kblk = blockIdx.x;
    int by, bx;
    if (kblk < (TTILES * (TTILES - 1)) / 2) {
        int e = (int)((63.0f - sqrtf(3969.0f - 8.0f * (float)kblk)) * 0.5f);
        while ((e + 1) * (TTILES - 1) - ((e + 1) * e) / 2 <= kblk) e++;
        while (e * (TTILES - 1) - (e * (e - 1)) / 2 > kblk) e--;
        by = e;
        bx = by + 1 + (kblk - (by * (TTILES - 1) - (by * (by - 1)) / 2));
    } else {
        by = bx = kblk - (TTILES * (TTILES - 1)) / 2;
    }
    const bool offDiag = (bx != by);
    int rowA = by * 128, rowB = bx * 128;

    extern __shared__ char smc[];
    __nv_bfloat16* Asm = (__nv_bfloat16*)(smc + SM_ASM);   // [2][128*40]
    __nv_bfloat16* Bsm = (__nv_bfloat16*)(smc + SM_BSM);   // [2][128*40]
    float* Dp = (float*)(smc + SM_DP);                     // 256 rows, stride 9

    int tid = threadIdx.x;
    int w = tid >> 5, lane = tid & 31;
    int wr = w & 1, wc = w >> 1;            // warp tile: rows wr*64, cols wc*32
    int g = lane >> 2, t4 = lane & 3;

    // stage positive-distance tables (stride 9 to de-conflict dp[ridx] LDS)
    if (tid < 256) {
        int r = tid & 127, which = tid >> 7;
        const float* src = &g_dpos[((which ? rowB : rowA) + r) * 8];
        float* dst = &Dp[(which * 128 + r) * 9];
        #pragma unroll
        for (int k = 0; k < 8; k++) dst[k] = src[k];
    }

    float acc[4][4][4];
    #pragma unroll
    for (int mt = 0; mt < 4; mt++)
        #pragma unroll
        for (int nt = 0; nt < 4; nt++)
            #pragma unroll
            for (int e = 0; e < 4; e++) acc[mt][nt][e] = 0.0f;

    unsigned aBase = (unsigned)__cvta_generic_to_shared(Asm);
    unsigned bBase = (unsigned)__cvta_generic_to_shared(Bsm);
    unsigned aAddr = aBase +
        (((unsigned)(wr * 64 + (lane & 15)) * 40 + ((lane & 16) ? 8u : 0u)) << 1);
    unsigned bAddr = bBase +
        (((unsigned)(wc * 32 + ((lane >> 4) & 1) * 8 + (lane & 7)) * 40 +
          ((lane & 8) ? 8u : 0u)) << 1);
    const unsigned BUFB = 128u * 40u * 2u;   // bytes per stage buffer

    // per-thread load slots: chunks tid*2, tid*2+1 of 512 16B-chunks per tile
    int lr0 = (tid * 2) >> 2,     lc0 = (tid * 2) & 3;
    int lr1 = (tid * 2 + 1) >> 2, lc1 = (tid * 2 + 1) & 3;

    const int NIT = DDIM / 32;   // 32 iterations

    // prologue: stage 0
    {
        cp16(&Asm[lr0 * 40 + lc0 * 8], &g_xb[(size_t)(rowA + lr0) * DDIM + lc0 * 8]);
        cp16(&Asm[lr1 * 40 + lc1 * 8], &g_xb[(size_t)(rowA + lr1) * DDIM + lc1 * 8]);
        cp16(&Bsm[lr0 * 40 + lc0 * 8], &g_xb[(size_t)(rowB + lr0) * DDIM + lc0 * 8]);
        cp16(&Bsm[lr1 * 40 + lc1 * 8], &g_xb[(size_t)(rowB + lr1) * DDIM + lc1 * 8]);
        asm volatile("cp.async.commit_group;\n");
    }

    for (int it = 0; it < NIT; it++) {
        if (it + 1 < NIT) {
            int k0n = (it + 1) * 32;
            unsigned bo = (unsigned)((it + 1) & 1) * (128 * 40);
            cp16(&Asm[bo + lr0 * 40 + lc0 * 8], &g_xb[(size_t)(rowA + lr0) * DDIM + k0n + lc0 * 8]);
            cp16(&Asm[bo + lr1 * 40 + lc1 * 8], &g_xb[(size_t)(rowA + lr1) * DDIM + k0n + lc1 * 8]);
            cp16(&Bsm[bo + lr0 * 40 + lc0 * 8], &g_xb[(size_t)(rowB + lr0) * DDIM + k0n + lc0 * 8]);
            cp16(&Bsm[bo + lr1 * 40 + lc1 * 8], &g_xb[(size_t)(rowB + lr1) * DDIM + k0n + lc1 * 8]);
            asm volatile("cp.async.commit_group;\n");
            asm volatile("cp.async.wait_group 1;\n");
        } else {
            asm volatile("cp.async.wait_group 0;\n");
        }
        __syncthreads();

        unsigned bufOff = (unsigned)(it & 1) * BUFB;
        #pragma unroll
        for (int s = 0; s < 2; s++) {         // two k16 steps per BK=32
            unsigned bf[4][2];
            #pragma unroll
            for (int ntp = 0; ntp < 2; ntp++) {
                unsigned r0, r1, r2, r3;
                asm volatile(
                    "ldmatrix.sync.aligned.m8n8.x4.shared.b16 {%0,%1,%2,%3}, [%4];"
                    : "=r"(r0), "=r"(r1), "=r"(r2), "=r"(r3)
                    : "r"(bAddr + bufOff + (unsigned)((ntp * 16 * 40 + s * 16) * 2)));
                bf[2 * ntp][0] = r0; bf[2 * ntp][1] = r1;
                bf[2 * ntp + 1][0] = r2; bf[2 * ntp + 1][1] = r3;
            }
            #pragma unroll
            for (int mt = 0; mt < 4; mt++) {
                unsigned a0, a1, a2, a3;
                asm volatile(
                    "ldmatrix.sync.aligned.m8n8.x4.shared.b16 {%0,%1,%2,%3}, [%4];"
                    : "=r"(a0), "=r"(a1), "=r"(a2), "=r"(a3)
                    : "r"(aAddr + bufOff + (unsigned)((mt * 16 * 40 + s * 16) * 2)));
                #pragma unroll
                for (int nt = 0; nt < 4; nt++) {
                    asm volatile(
                        "mma.sync.aligned.m16n8k16.row.col.f32.bf16.bf16.f32 "
                        "{%0,%1,%2,%3}, {%4,%5,%6,%7}, {%8,%9}, {%0,%1,%2,%3};"
                        : "+f"(acc[mt][nt][0]), "+f"(acc[mt][nt][1]),
                          "+f"(acc[mt][nt][2]), "+f"(acc[mt][nt][3])
                        : "r"(a0), "r"(a1), "r"(a2), "r"(a3),
                          "r"(bf[nt][0]), "r"(bf[nt][1]));
                }
            }
        }
        __syncthreads();
    }

    // ---------------- table-driven epilogue ----------------
    // Thread-invariant facts: i&7 == g for all its anchors; j&7 == 2*t4+ch.
    const int jq0 = 2 * t4, jq1 = 2 * t4 + 1;
    const bool fwd_ok = (g < 7);                 // pi(i) = 7-g > 0
    const int pj0 = 7 - jq0, pj1 = 7 - jq1;      // pi(j) per ch
    float lsum = 0.0f;

    #pragma unroll 2
    for (int mr = 0; mr < 8; mr++) {
        int mt = mr >> 1, rh = mr & 1;
        int il = wr * 64 + mt * 16 + rh * 8 + g;
        int i = rowA + il;
        int c = i >> 3;
        const float* dpi = &Dp[il * 9];
        #pragma unroll
        for (int nt = 0; nt < 4; nt++) {
            int jb = rowB + wc * 32 + nt * 8;    // class block base (mult of 8)
            int cj = jb >> 3;
            if (c == cj) continue;               // same class: no negatives here
            int dd = abs(c - cj);
            int before = max(0, c - dd) + max(0, (NCLS - 1) - c - dd)
                       + ((cj > c && c >= dd) ? 1 : 0);
            int tb = before << 3;
            int before_r = max(0, cj - dd) + max(0, (NCLS - 1) - cj - dd)
                         + ((c > cj && cj >= dd) ? 1 : 0);
            int t_r = (before_r << 3) + g;       // anchor j, negative i
            bool rev_ok = offDiag && (t_r < NNEGS);
            const float* dpj = &Dp[(128 + wc * 32 + nt * 8) * 9];
            #pragma unroll
            for (int ch = 0; ch < 2; ch++) {
                int jq = ch ? jq1 : jq0;
                int j = jb + jq;
                float s = acc[mt][nt][rh * 2 + ch];
                int tf = tb + jq;
                if (fwd_ok && tf < NNEGS) {
                    int ridx = (int)__ldg(&g_rsel[(unsigned)tf * NROWS + (unsigned)i]);
                    lsum += fmaxf(dpi[ridx] + s + (MARGINF - 1.0f), 0.0f);
                }
                int pj = ch ? pj1 : pj0;
                if (rev_ok && pj > 0) {
                    int ridx = (int)__ldg(&g_rsel[(unsigned)t_r * NROWS + (unsigned)j]);
                    lsum += fmaxf(dpj[jq * 9 + ridx] + s + (MARGINF - 1.0f), 0.0f);
                }
            }
        }
    }

    // block reduction -> one atomicAdd per CTA (reuse Dp as scratch)
    #pragma unroll
    for (int o = 16; o; o >>= 1) lsum += __shfl_down_sync(0xffffffffu, lsum, o);
    __syncthreads();                       // everyone done reading Dp
    if ((tid & 31) == 0) Dp[tid >> 5] = lsum;
    __syncthreads();
    if (tid < 8) {
        float s2 = Dp[tid];
        #pragma unroll
        for (int o = 4; o; o >>= 1) s2 += __shfl_down_sync(0xffu, s2, o);
        if (tid == 0) atomicAdd(out, s2);
    }
}

// ---------------------------------------------------------------------------
extern "C" void kernel_launch(void* const* d_in, const int* in_sizes, int n_in,
                              void* d_out, int out_size) {
    const float* samples = (const float*)d_in[0];
    float* out = (float*)d_out;

    static int smem_set = 0;
    if (!smem_set) {
        cudaFuncSetAttribute(loss_kernel,
                             cudaFuncAttributeMaxDynamicSharedMemorySize, SM_TOTAL);
        smem_set = 1;
    }
    normalize_kernel<<<NROWS, 256>>>(samples, out, out_size);
    posdist_kernel<<<NCLS, 256>>>();
    rng_kernel<<<(NNEGS * 2048) / 256, 256>>>();
    loss_kernel<<<(TTILES * (TTILES + 1)) / 2, 256, SM_TOTAL>>>(out);
}

// round 8
// speedup vs baseline: 2.1934x; 2.1934x over previous
#include <cuda_runtime.h>
#include <cuda_bf16.h>
#include <cstdint>

// Problem constants (fixed by the dataset instance)
#define NROWS  4096
#define DDIM   1024
#define NCLS   512
#define NNEGS  3679
#define HHALF  7534592u        // n/2 for threefry lane pairing, n = 4096*3679
#define MARGINF 0.15f
#define TTILES 32              // 4096 / 128

// loss kernel dynamic smem layout (bytes)
#define STG_BYTES 10240                 // one stage, one matrix: 128*40*2
#define SM_ASM   0                      // 3 stages A: [0, 30720)
#define SM_BSM   30720                  // 3 stages B: [30720, 61440)
#define SM_DP    61440                  // Dp: 256 rows * 9 floats = 9216
#define SM_TOTAL 70656
// epilogue staging overlays (reuse stage buffers after mainloop)
#define SM_RF    0                      // fwd bands, 16 KB
#define SM_RR    30720                  // rev bands, 16 KB

// prep kernel grid split
#define PREP_NORM 4096
#define PREP_POS  (PREP_NORM + NCLS)              // 4608
#define PREP_RNG_BLKS ((NNEGS * 2048) / 256)      // 29432
#define PREP_GRID (PREP_POS + PREP_RNG_BLKS)

// Scratch (static __device__ arrays: allocation-free)
__device__ __nv_bfloat16 g_xb[NROWS * DDIM];    // normalized samples, bf16
__device__ float g_dpos[NROWS * 8];             // per-row positive distances
__device__ unsigned char g_rsel[NNEGS * NROWS]; // resample idx, t-major [t][i]

// ---------------------------------------------------------------------------
// Threefry-2x32-20, key (0, 42), exact JAX semantics; returns both words.
// ---------------------------------------------------------------------------
__device__ __forceinline__ void tf_block(unsigned lane, unsigned& o0, unsigned& o1) {
    const unsigned ks1 = 42u;
    const unsigned ks2 = 0x1BD11BDAu ^ 42u;
    unsigned x0 = lane;
    unsigned x1 = lane + HHALF + ks1;
#define TFR(r) { x0 += x1; x1 = (x1 << (r)) | (x1 >> (32 - (r))); x1 ^= x0; }
    TFR(13) TFR(15) TFR(26) TFR(6)   x0 += ks1; x1 += ks2 + 1u;
    TFR(17) TFR(29) TFR(16) TFR(24)  x0 += ks2; x1 += 0u  + 2u;
    TFR(13) TFR(15) TFR(26) TFR(6)   x0 += 0u;  x1 += ks1 + 3u;
    TFR(17) TFR(29) TFR(16) TFR(24)  x0 += ks1; x1 += ks2 + 4u;
    TFR(13) TFR(15) TFR(26) TFR(6)   x0 += ks2; x1 += 0u  + 5u;
#undef TFR
    o0 = x0; o1 = x1;
}

__device__ __forceinline__ float bits_to_u(unsigned bits) {
    return __uint_as_float((bits >> 9) | 0x3F800000u) - 1.0f;
}

__device__ __forceinline__ void cp16(unsigned sa, const void* g) {
    asm volatile("cp.async.cg.shared.global [%0], [%1], 16;\n" :: "r"(sa), "l"(g));
}

// ---------------------------------------------------------------------------
// Prep kernel: three independent sections run concurrently in one launch.
//   blocks [0, 4096)      : row L2-normalize -> g_xb (bf16); block 0 zeroes out
//   blocks [4096, 4608)   : per-class positive distances from RAW samples
//   blocks [4608, 34040)  : threefry rng table (pair-folded, t-major)
// ---------------------------------------------------------------------------
__global__ __launch_bounds__(256) void prep_kernel(const float* __restrict__ x,
                                                   float* __restrict__ out,
                                                   int out_size) {
    __shared__ float sm[8 * DDIM + 16];
    int bid = blockIdx.x;
    int tid = threadIdx.x;

    if (bid < PREP_NORM) {
        // ---- normalize one row ----
        if (bid == 0 && tid == 0)
            for (int i = 0; i < out_size; i++) out[i] = 0.0f;
        const float4* xin = (const float4*)(x + (size_t)bid * DDIM);
        float4 v = xin[tid];
        float ss = v.x * v.x + v.y * v.y + v.z * v.z + v.w * v.w;
        #pragma unroll
        for (int o = 16; o; o >>= 1) ss += __shfl_down_sync(0xffffffffu, ss, o);
        if ((tid & 31) == 0) sm[8 * DDIM + (tid >> 5)] = ss;
        __syncthreads();
        if (tid < 8) {
            float s2 = sm[8 * DDIM + tid];
            #pragma unroll
            for (int o = 4; o; o >>= 1) s2 += __shfl_down_sync(0xffu, s2, o);
            if (tid == 0) sm[8 * DDIM] = s2;
        }
        __syncthreads();
        float scale = 1.0f / fmaxf(sqrtf(sm[8 * DDIM]), 1e-8f);
        __nv_bfloat16 b[4];
        b[0] = __float2bfloat16(v.x * scale);
        b[1] = __float2bfloat16(v.y * scale);
        b[2] = __float2bfloat16(v.z * scale);
        b[3] = __float2bfloat16(v.w * scale);
        *(uint2*)(g_xb + (size_t)bid * DDIM + tid * 4) = *(uint2*)b;
    } else if (bid < PREP_POS) {
        // ---- positive distances for one class, self-normalizing ----
        int cls = bid - PREP_NORM;
        const float4* src = (const float4*)(x + (size_t)cls * 8 * DDIM);
        float4* dst = (float4*)sm;
        #pragma unroll
        for (int idx = tid; idx < 8 * DDIM / 4; idx += 256) dst[idx] = src[idx];
        __syncthreads();
        int w = tid >> 5, lane = tid & 31;
        // warp w: inverse norm of row w
        {
            float s = 0.f;
            for (int e = lane; e < DDIM; e += 32) {
                float t = sm[w * DDIM + e];
                s += t * t;
            }
            #pragma unroll
            for (int o = 16; o; o >>= 1) s += __shfl_down_sync(0xffffffffu, s, o);
            if (lane == 0) sm[8 * DDIM + w] = 1.0f / fmaxf(sqrtf(s), 1e-8f);
        }
        __syncthreads();
        for (int q = w; q < 28; q += 8) {
            int a = 0, rem = q;
            while (rem >= 7 - a) { rem -= 7 - a; a++; }
            int b = a + 1 + rem;
            float s = 0.f;
            for (int e = lane; e < DDIM; e += 32) s += sm[a * DDIM + e] * sm[b * DDIM + e];
            #pragma unroll
            for (int o = 16; o; o >>= 1) s += __shfl_down_sync(0xffffffffu, s, o);
            if (lane == 0)
                g_dpos[(cls * 8 + a) * 8 + (b - a - 1)] =
                    1.0f - s * sm[8 * DDIM + a] * sm[8 * DDIM + b];
        }
    } else {
        // ---- rng table; g = t*2048 + i_low, one block serves i_low & i_low+2048
        unsigned g = (unsigned)(bid - PREP_POS) * 256u + (unsigned)tid;
        unsigned t = g >> 11;
        unsigned i_low = g & 2047u;
        int pi = 7 - (int)(i_low & 7u);
        if (pi == 0) {
            g_rsel[t * NROWS + i_low] = 0xFFu;
            g_rsel[t * NROWS + i_low + 2048] = 0xFFu;
            return;
        }
        unsigned f = i_low * NNEGS + t;                  // f < HHALF
        unsigned x0, x1;
        tf_block(f, x0, x1);
        float pf = (float)pi;
        int r0 = min((int)(bits_to_u(x0) * pf), pi - 1);
        int r1 = min((int)(bits_to_u(x1) * pf), pi - 1);
        g_rsel[t * NROWS + i_low] = (unsigned char)r0;
        g_rsel[t * NROWS + i_low + 2048] = (unsigned char)r1;
    }
}

// ---------------------------------------------------------------------------
// Loss kernel: bf16 mma.sync Gram (triangular grid, 528 CTAs, off-diagonal
// first), 3-stage cp.async pipeline (1 sync/iter), then cooperative band
// staging of the rsel table into smem + fully-unrolled cheap epilogue.
// CTA = 128x128 tile, 8 warps, each warp 64x32 via m16n8k16 mma.sync.
// ---------------------------------------------------------------------------
__global__ __launch_bounds__(256, 2) void loss_kernel(float* __restrict__ out) {
    // decode blockIdx.x -> (by, bx), bx >= by; off-diagonal pairs first
    int kblk = blockIdx.x;
    int by, bx;
    if (kblk < (TTILES * (TTILES - 1)) / 2) {
        int e = (int)((63.0f - sqrtf(3969.0f - 8.0f * (float)kblk)) * 0.5f);
        while ((e + 1) * (TTILES - 1) - ((e + 1) * e) / 2 <= kblk) e++;
        while (e * (TTILES - 1) - (e * (e - 1)) / 2 > kblk) e--;
        by = e;
        bx = by + 1 + (kblk - (by * (TTILES - 1) - (by * (by - 1)) / 2));
    } else {
        by = bx = kblk - (TTILES * (TTILES - 1)) / 2;
    }
    const bool offDiag = (bx != by);
    int rowA = by * 128, rowB = bx * 128;

    extern __shared__ char smc[];
    float* Dp = (float*)(smc + SM_DP);                     // 256 rows, stride 9

    int tid = threadIdx.x;
    int w = tid >> 5, lane = tid & 31;
    int wr = w & 1, wc = w >> 1;            // warp tile: rows wr*64, cols wc*32
    int g = lane >> 2, t4 = lane & 3;

    // stage positive-distance tables (stride 9 to de-conflict dp[ridx] LDS)
    {
        int r = tid & 127, which = tid >> 7;
        const float* src = &g_dpos[((which ? rowB : rowA) + r) * 8];
        float* dst = &Dp[(which * 128 + r) * 9];
        #pragma unroll
        for (int k = 0; k < 8; k++) dst[k] = src[k];
    }

    float acc[4][4][4];
    #pragma unroll
    for (int mt = 0; mt < 4; mt++)
        #pragma unroll
        for (int nt = 0; nt < 4; nt++)
            #pragma unroll
            for (int e = 0; e < 4; e++) acc[mt][nt][e] = 0.0f;

    unsigned aBase = (unsigned)__cvta_generic_to_shared(smc + SM_ASM);
    unsigned bBase = (unsigned)__cvta_generic_to_shared(smc + SM_BSM);
    unsigned aAddr = aBase +
        (((unsigned)(wr * 64 + (lane & 15)) * 40 + ((lane & 16) ? 8u : 0u)) << 1);
    unsigned bAddr = bBase +
        (((unsigned)(wc * 32 + ((lane >> 4) & 1) * 8 + (lane & 7)) * 40 +
          ((lane & 8) ? 8u : 0u)) << 1);

    // per-thread load slots: chunks tid*2, tid*2+1 of 512 16B-chunks per tile
    int lr0 = (tid * 2) >> 2,     lc0 = (tid * 2) & 3;
    int lr1 = (tid * 2 + 1) >> 2, lc1 = (tid * 2 + 1) & 3;
    unsigned sa0 = (unsigned)(lr0 * 40 + lc0 * 8) * 2u;
    unsigned sa1 = (unsigned)(lr1 * 40 + lc1 * 8) * 2u;

    const int NIT = DDIM / 32;   // 32 iterations

    #define LOAD_STAGE(sidx, k0) do {                                          \
        unsigned ao = aBase + (unsigned)(sidx) * STG_BYTES;                    \
        unsigned bo = bBase + (unsigned)(sidx) * STG_BYTES;                    \
        cp16(ao + sa0, &g_xb[(size_t)(rowA + lr0) * DDIM + (k0) + lc0 * 8]);   \
        cp16(ao + sa1, &g_xb[(size_t)(rowA + lr1) * DDIM + (k0) + lc1 * 8]);   \
        cp16(bo + sa0, &g_xb[(size_t)(rowB + lr0) * DDIM + (k0) + lc0 * 8]);   \
        cp16(bo + sa1, &g_xb[(size_t)(rowB + lr1) * DDIM + (k0) + lc1 * 8]);   \
        asm volatile("cp.async.commit_group;\n" ::: "memory");                 \
    } while (0)

    LOAD_STAGE(0, 0);
    LOAD_STAGE(1, 32);

    for (int it = 0; it < NIT; it++) {
        if (it < NIT - 1) asm volatile("cp.async.wait_group 1;\n" ::: "memory");
        else              asm volatile("cp.async.wait_group 0;\n" ::: "memory");
        __syncthreads();
        if (it + 2 < NIT) LOAD_STAGE((it + 2) % 3, (it + 2) * 32);

        unsigned bufOff = (unsigned)(it % 3) * STG_BYTES;
        #pragma unroll
        for (int s = 0; s < 2; s++) {         // two k16 steps per BK=32
            unsigned bf[4][2];
            #pragma unroll
            for (int ntp = 0; ntp < 2; ntp++) {
                unsigned r0, r1, r2, r3;
                asm volatile(
                    "ldmatrix.sync.aligned.m8n8.x4.shared.b16 {%0,%1,%2,%3}, [%4];"
                    : "=r"(r0), "=r"(r1), "=r"(r2), "=r"(r3)
                    : "r"(bAddr + bufOff + (unsigned)((ntp * 16 * 40 + s * 16) * 2)));
                bf[2 * ntp][0] = r0; bf[2 * ntp][1] = r1;
                bf[2 * ntp + 1][0] = r2; bf[2 * ntp + 1][1] = r3;
            }
            #pragma unroll
            for (int mt = 0; mt < 4; mt++) {
                unsigned a0, a1, a2, a3;
                asm volatile(
                    "ldmatrix.sync.aligned.m8n8.x4.shared.b16 {%0,%1,%2,%3}, [%4];"
                    : "=r"(a0), "=r"(a1), "=r"(a2), "=r"(a3)
                    : "r"(aAddr + bufOff + (unsigned)((mt * 16 * 40 + s * 16) * 2)));
                #pragma unroll
                for (int nt = 0; nt < 4; nt++) {
                    asm volatile(
                        "mma.sync.aligned.m16n8k16.row.col.f32.bf16.bf16.f32 "
                        "{%0,%1,%2,%3}, {%4,%5,%6,%7}, {%8,%9}, {%0,%1,%2,%3};"
                        : "+f"(acc[mt][nt][0]), "+f"(acc[mt][nt][1]),
                          "+f"(acc[mt][nt][2]), "+f"(acc[mt][nt][3])
                        : "r"(a0), "r"(a1), "r"(a2), "r"(a3),
                          "r"(bf[nt][0]), "r"(bf[nt][1]));
                }
            }
        }
        __syncthreads();   // protect stage reuse (prefetch of it+2 next iter)
    }

    // ---------------- cooperative band staging ----------------
    // fwd band (c_l, cj_l): 8x8 bytes, chunk (jo): rsel[(bef*8+jo)*4096 + rowA + c_l*8 .. +7]
    // rev band (c_l, cj_l): chunk (io): rsel[(befr*8+io)*4096 + rowB + cj_l*8 .. +7]
    // invalid chunks (same class / t >= NNEGS / non-offDiag rev) -> 0xFF sentinel
    unsigned char* RF = (unsigned char*)(smc + SM_RF);
    unsigned char* RR = (unsigned char*)(smc + SM_RR);
    #pragma unroll
    for (int ss = 0; ss < 8; ss++) {
        int cid = tid + ss * 256;                 // 0..2047
        int c_l = cid >> 7, cj_l = (cid >> 3) & 15, jo = cid & 7;
        int c = by * 16 + c_l, cj = bx * 16 + cj_l;
        int dd = abs(c - cj);
        int bef = max(0, c - dd) + max(0, (NCLS - 1) - c - dd)
                + ((cj > c && c >= dd) ? 1 : 0);
        int t = bef * 8 + jo;
        uint2 v = make_uint2(0xFFFFFFFFu, 0xFFFFFFFFu);
        if (c != cj && t < NNEGS)
            v = *(const uint2*)&g_rsel[(unsigned)t * NROWS + (unsigned)(rowA + c_l * 8)];
        *(uint2*)&RF[cid * 8] = v;

        int befr = max(0, cj - dd) + max(0, (NCLS - 1) - cj - dd)
                 + ((c > cj && cj >= dd) ? 1 : 0);
        int tr = befr * 8 + jo;                   // jo plays the role of io
        uint2 vr = make_uint2(0xFFFFFFFFu, 0xFFFFFFFFu);
        if (offDiag && tr < NNEGS)
            vr = *(const uint2*)&g_rsel[(unsigned)tr * NROWS + (unsigned)(rowB + cj_l * 8)];
        *(uint2*)&RR[cid * 8] = vr;
    }
    __syncthreads();

    // ---------------- fully-unrolled epilogue ----------------
    const float MC = MARGINF - 1.0f;
    float lsum = 0.0f;
    #pragma unroll
    for (int mr = 0; mr < 8; mr++) {
        int mt = mr >> 1, rh = mr & 1;
        int c_l = wr * 8 + mt * 2 + rh;
        int il = c_l * 8 + g;
        const float* dpi = &Dp[il * 9];
        #pragma unroll
        for (int nt = 0; nt < 4; nt++) {
            int cj_l = wc * 4 + nt;
            const unsigned char* bF = &RF[(c_l * 16 + cj_l) * 64];
            const unsigned char* bR = &RR[(c_l * 16 + cj_l) * 64];
            #pragma unroll
            for (int ch = 0; ch < 2; ch++) {
                int jq = 2 * t4 + ch;
                float s = acc[mt][nt][rh * 2 + ch];
                int rf = bF[jq * 8 + g];
                if (rf != 255)
                    lsum += fmaxf(dpi[rf] + s + MC, 0.0f);
                if (offDiag) {
                    int rr = bR[g * 8 + jq];
                    if (rr != 255) {
                        int jl = wc * 32 + nt * 8 + jq;
                        lsum += fmaxf(Dp[(128 + jl) * 9 + rr] + s + MC, 0.0f);
                    }
                }
            }
        }
    }

    // block reduction -> one atomicAdd per CTA (reuse Dp as scratch)
    #pragma unroll
    for (int o = 16; o; o >>= 1) lsum += __shfl_down_sync(0xffffffffu, lsum, o);
    __syncthreads();                       // everyone done reading Dp
    if ((tid & 31) == 0) Dp[tid >> 5] = lsum;
    __syncthreads();
    if (tid < 8) {
        float s2 = Dp[tid];
        #pragma unroll
        for (int o = 4; o; o >>= 1) s2 += __shfl_down_sync(0xffu, s2, o);
        if (tid == 0) atomicAdd(out, s2);
    }
}

// ---------------------------------------------------------------------------
extern "C" void kernel_launch(void* const* d_in, const int* in_sizes, int n_in,
                              void* d_out, int out_size) {
    const float* samples = (const float*)d_in[0];
    float* out = (float*)d_out;

    cudaFuncSetAttribute(loss_kernel,
                         cudaFuncAttributeMaxDynamicSharedMemorySize, SM_TOTAL);
    prep_kernel<<<PREP_GRID, 256>>>(samples, out, out_size);
    loss_kernel<<<(TTILES * (TTILES + 1)) / 2, 256, SM_TOTAL>>>(out);
}

// round 10
// speedup vs baseline: 2.4865x; 1.1336x over previous
#include <cuda_runtime.h>
#include <cuda_bf16.h>
#include <cstdint>

// Problem constants (fixed by the dataset instance)
#define NROWS  4096
#define DDIM   1024
#define NCLS   512
#define NNEGS  3679
#define HHALF  7534592u        // n/2 for threefry lane pairing, n = 4096*3679
#define MARGINF 0.15f
#define TTILES 32              // 4096 / 128

// loss kernel dynamic smem layout (bytes)
#define STG_BYTES 10240                 // one stage, one matrix: 128*40*2
#define SM_ASM   0                      // 3 stages A: [0, 30720)
#define SM_BSM   30720                  // 3 stages B: [30720, 61440)
#define SM_DP    61440                  // Dp: 256 rows * 9 floats = 9216
#define SM_TOTAL 70656
// epilogue staging overlays (reuse stage buffers after mainloop)
#define SM_RF    0                      // fwd bands, 16 KB
#define SM_RR    30720                  // rev bands, 16 KB

// prep kernel grid split
#define PREP_NORM 4096
#define PREP_POS  (PREP_NORM + NCLS)              // 4608
#define PREP_RNG_BLKS ((NNEGS * 2048) / 256)      // 29432
#define PREP_GRID (PREP_POS + PREP_RNG_BLKS)

// Scratch (static __device__ arrays: allocation-free)
__device__ __nv_bfloat16 g_xb[NROWS * DDIM];    // normalized samples, bf16
__device__ float g_dpos[NROWS * 8];             // per-row positive distances
__device__ unsigned char g_rsel[NNEGS * NROWS]; // resample idx, t-major [t][i]

// ---------------------------------------------------------------------------
// Threefry-2x32-20, key (0, 42), exact JAX semantics; returns both words.
// ---------------------------------------------------------------------------
__device__ __forceinline__ void tf_block(unsigned lane, unsigned& o0, unsigned& o1) {
    const unsigned ks1 = 42u;
    const unsigned ks2 = 0x1BD11BDAu ^ 42u;
    unsigned x0 = lane;
    unsigned x1 = lane + HHALF + ks1;
#define TFR(r) { x0 += x1; x1 = (x1 << (r)) | (x1 >> (32 - (r))); x1 ^= x0; }
    TFR(13) TFR(15) TFR(26) TFR(6)   x0 += ks1; x1 += ks2 + 1u;
    TFR(17) TFR(29) TFR(16) TFR(24)  x0 += ks2; x1 += 0u  + 2u;
    TFR(13) TFR(15) TFR(26) TFR(6)   x0 += 0u;  x1 += ks1 + 3u;
    TFR(17) TFR(29) TFR(16) TFR(24)  x0 += ks1; x1 += ks2 + 4u;
    TFR(13) TFR(15) TFR(26) TFR(6)   x0 += ks2; x1 += 0u  + 5u;
#undef TFR
    o0 = x0; o1 = x1;
}

__device__ __forceinline__ float bits_to_u(unsigned bits) {
    return __uint_as_float((bits >> 9) | 0x3F800000u) - 1.0f;
}

__device__ __forceinline__ void cp16(unsigned sa, const void* g) {
    asm volatile("cp.async.cg.shared.global [%0], [%1], 16;\n" :: "r"(sa), "l"(g));
}

// ---------------------------------------------------------------------------
// Prep kernel: three independent sections run concurrently in one launch.
//   blocks [0, 4096)      : row L2-normalize -> g_xb (bf16); block 0 zeroes out
//   blocks [4096, 4608)   : per-class positive distances from RAW samples
//   blocks [4608, 34040)  : threefry rng table (pair-folded, t-major)
// ---------------------------------------------------------------------------
__global__ __launch_bounds__(256) void prep_kernel(const float* __restrict__ x,
                                                   float* __restrict__ out,
                                                   int out_size) {
    __shared__ float sm[8 * DDIM + 16];
    int bid = blockIdx.x;
    int tid = threadIdx.x;

    if (bid < PREP_NORM) {
        // ---- normalize one row ----
        if (bid == 0 && tid == 0)
            for (int i = 0; i < out_size; i++) out[i] = 0.0f;
        const float4* xin = (const float4*)(x + (size_t)bid * DDIM);
        float4 v = xin[tid];
        float ss = v.x * v.x + v.y * v.y + v.z * v.z + v.w * v.w;
        #pragma unroll
        for (int o = 16; o; o >>= 1) ss += __shfl_down_sync(0xffffffffu, ss, o);
        if ((tid & 31) == 0) sm[8 * DDIM + (tid >> 5)] = ss;
        __syncthreads();
        if (tid < 8) {
            float s2 = sm[8 * DDIM + tid];
            #pragma unroll
            for (int o = 4; o; o >>= 1) s2 += __shfl_down_sync(0xffu, s2, o);
            if (tid == 0) sm[8 * DDIM] = s2;
        }
        __syncthreads();
        float scale = 1.0f / fmaxf(sqrtf(sm[8 * DDIM]), 1e-8f);
        __nv_bfloat16 b[4];
        b[0] = __float2bfloat16(v.x * scale);
        b[1] = __float2bfloat16(v.y * scale);
        b[2] = __float2bfloat16(v.z * scale);
        b[3] = __float2bfloat16(v.w * scale);
        *(uint2*)(g_xb + (size_t)bid * DDIM + tid * 4) = *(uint2*)b;
    } else if (bid < PREP_POS) {
        // ---- positive distances for one class, self-normalizing ----
        int cls = bid - PREP_NORM;
        const float4* src = (const float4*)(x + (size_t)cls * 8 * DDIM);
        float4* dst = (float4*)sm;
        #pragma unroll
        for (int idx = tid; idx < 8 * DDIM / 4; idx += 256) dst[idx] = src[idx];
        __syncthreads();
        int w = tid >> 5, lane = tid & 31;
        // warp w: inverse norm of row w
        {
            float s = 0.f;
            for (int e = lane; e < DDIM; e += 32) {
                float t = sm[w * DDIM + e];
                s += t * t;
            }
            #pragma unroll
            for (int o = 16; o; o >>= 1) s += __shfl_down_sync(0xffffffffu, s, o);
            if (lane == 0) sm[8 * DDIM + w] = 1.0f / fmaxf(sqrtf(s), 1e-8f);
        }
        __syncthreads();
        for (int q = w; q < 28; q += 8) {
            int a = 0, rem = q;
            while (rem >= 7 - a) { rem -= 7 - a; a++; }
            int b = a + 1 + rem;
            float s = 0.f;
            for (int e = lane; e < DDIM; e += 32) s += sm[a * DDIM + e] * sm[b * DDIM + e];
            #pragma unroll
            for (int o = 16; o; o >>= 1) s += __shfl_down_sync(0xffffffffu, s, o);
            if (lane == 0)
                g_dpos[(cls * 8 + a) * 8 + (b - a - 1)] =
                    1.0f - s * sm[8 * DDIM + a] * sm[8 * DDIM + b];
        }
    } else {
        // ---- rng table; g = t*2048 + i_low, one block serves i_low & i_low+2048
        unsigned g = (unsigned)(bid - PREP_POS) * 256u + (unsigned)tid;
        unsigned t = g >> 11;
        unsigned i_low = g & 2047u;
        int pi = 7 - (int)(i_low & 7u);
        if (pi == 0) {
            g_rsel[t * NROWS + i_low] = 0xFFu;
            g_rsel[t * NROWS + i_low + 2048] = 0xFFu;
            return;
        }
        unsigned f = i_low * NNEGS + t;                  // f < HHALF
        unsigned x0, x1;
        tf_block(f, x0, x1);
        float pf = (float)pi;
        int r0 = min((int)(bits_to_u(x0) * pf), pi - 1);
        int r1 = min((int)(bits_to_u(x1) * pf), pi - 1);
        g_rsel[t * NROWS + i_low] = (unsigned char)r0;
        g_rsel[t * NROWS + i_low + 2048] = (unsigned char)r1;
    }
}

// ---------------------------------------------------------------------------
// Loss kernel: bf16 mma.sync Gram (triangular grid, 528 CTAs, off-diagonal
// first), 3-stage cp.async pipeline with ONE __syncthreads per iteration,
// then cooperative band staging of the rsel table + cheap unrolled epilogue.
// CTA = 128x128 tile, 512 threads, 16 warps, each warp 32x32 via m16n8k16.
// 64 regs/thread -> 2 CTAs/SM -> 32 warps/SM (vs 16 before).
// ---------------------------------------------------------------------------
__global__ __launch_bounds__(512, 2) void loss_kernel(float* __restrict__ out) {
    // decode blockIdx.x -> (by, bx), bx >= by; off-diagonal pairs first
    int kblk = blockIdx.x;
    int by, bx;
    if (kblk < (TTILES * (TTILES - 1)) / 2) {
        int e = (int)((63.0f - sqrtf(3969.0f - 8.0f * (float)kblk)) * 0.5f);
        while ((e + 1) * (TTILES - 1) - ((e + 1) * e) / 2 <= kblk) e++;
        while (e * (TTILES - 1) - (e * (e - 1)) / 2 > kblk) e--;
        by = e;
        bx = by + 1 + (kblk - (by * (TTILES - 1) - (by * (by - 1)) / 2));
    } else {
        by = bx = kblk - (TTILES * (TTILES - 1)) / 2;
    }
    const bool offDiag = (bx != by);
    int rowA = by * 128, rowB = bx * 128;

    extern __shared__ char smc[];
    float* Dp = (float*)(smc + SM_DP);                     // 256 rows, stride 9

    int tid = threadIdx.x;
    int w = tid >> 5, lane = tid & 31;
    int wr = w & 3, wc = w >> 2;            // warp tile: rows wr*32, cols wc*32
    int g = lane >> 2, t4 = lane & 3;

    // stage positive-distance tables (stride 9 to de-conflict dp[ridx] LDS)
    if (tid < 256) {
        int r = tid & 127, which = tid >> 7;
        const float* src = &g_dpos[((which ? rowB : rowA) + r) * 8];
        float* dst = &Dp[(which * 128 + r) * 9];
        #pragma unroll
        for (int k = 0; k < 8; k++) dst[k] = src[k];
    }

    float acc[2][4][4];
    #pragma unroll
    for (int mt = 0; mt < 2; mt++)
        #pragma unroll
        for (int nt = 0; nt < 4; nt++)
            #pragma unroll
            for (int e = 0; e < 4; e++) acc[mt][nt][e] = 0.0f;

    unsigned aBase = (unsigned)__cvta_generic_to_shared(smc + SM_ASM);
    unsigned bBase = (unsigned)__cvta_generic_to_shared(smc + SM_BSM);
    unsigned aAddr = aBase +
        (((unsigned)(wr * 32 + (lane & 15)) * 40 + ((lane & 16) ? 8u : 0u)) << 1);
    unsigned bAddr = bBase +
        (((unsigned)(wc * 32 + ((lane >> 4) & 1) * 8 + (lane & 7)) * 40 +
          ((lane & 8) ? 8u : 0u)) << 1);

    // per-thread load slot: chunk tid of 512 16B-chunks per tile
    int lr = tid >> 2, lc = tid & 3;
    unsigned sa = (unsigned)(lr * 40 + lc * 8) * 2u;

    const int NIT = DDIM / 32;   // 32 iterations

    #define LOAD_STAGE(sidx, k0) do {                                          \
        unsigned ao = aBase + (unsigned)(sidx) * STG_BYTES;                    \
        unsigned bo = bBase + (unsigned)(sidx) * STG_BYTES;                    \
        cp16(ao + sa, &g_xb[(size_t)(rowA + lr) * DDIM + (k0) + lc * 8]);      \
        cp16(bo + sa, &g_xb[(size_t)(rowB + lr) * DDIM + (k0) + lc * 8]);      \
        asm volatile("cp.async.commit_group;\n" ::: "memory");                 \
    } while (0)

    LOAD_STAGE(0, 0);
    LOAD_STAGE(1, 32);

    for (int it = 0; it < NIT; it++) {
        if (it < NIT - 1) asm volatile("cp.async.wait_group 1;\n" ::: "memory");
        else              asm volatile("cp.async.wait_group 0;\n" ::: "memory");
        __syncthreads();
        // prefetch stage (it+2)%3 == stage (it-1)%3, whose reads finished
        // before the barrier above released (single sync per iteration).
        if (it + 2 < NIT) LOAD_STAGE((it + 2) % 3, (it + 2) * 32);

        unsigned bufOff = (unsigned)(it % 3) * STG_BYTES;
        #pragma unroll
        for (int s = 0; s < 2; s++) {         // two k16 steps per BK=32
            unsigned bf[4][2];
            #pragma unroll
            for (int ntp = 0; ntp < 2; ntp++) {
                unsigned r0, r1, r2, r3;
                asm volatile(
                    "ldmatrix.sync.aligned.m8n8.x4.shared.b16 {%0,%1,%2,%3}, [%4];"
                    : "=r"(r0), "=r"(r1), "=r"(r2), "=r"(r3)
                    : "r"(bAddr + bufOff + (unsigned)((ntp * 16 * 40 + s * 16) * 2)));
                bf[2 * ntp][0] = r0; bf[2 * ntp][1] = r1;
                bf[2 * ntp + 1][0] = r2; bf[2 * ntp + 1][1] = r3;
            }
            #pragma unroll
            for (int mt = 0; mt < 2; mt++) {
                unsigned a0, a1, a2, a3;
                asm volatile(
                    "ldmatrix.sync.aligned.m8n8.x4.shared.b16 {%0,%1,%2,%3}, [%4];"
                    : "=r"(a0), "=r"(a1), "=r"(a2), "=r"(a3)
                    : "r"(aAddr + bufOff + (unsigned)((mt * 16 * 40 + s * 16) * 2)));
                #pragma unroll
                for (int nt = 0; nt < 4; nt++) {
                    asm volatile(
                        "mma.sync.aligned.m16n8k16.row.col.f32.bf16.bf16.f32 "
                        "{%0,%1,%2,%3}, {%4,%5,%6,%7}, {%8,%9}, {%0,%1,%2,%3};"
                        : "+f"(acc[mt][nt][0]), "+f"(acc[mt][nt][1]),
                          "+f"(acc[mt][nt][2]), "+f"(acc[mt][nt][3])
                        : "r"(a0), "r"(a1), "r"(a2), "r"(a3),
                          "r"(bf[nt][0]), "r"(bf[nt][1]));
                }
            }
        }
    }
    __syncthreads();    // all warps done with stage buffers before overlay

    // ---------------- cooperative band staging ----------------
    // fwd band (c_l, cj_l), chunk jo: rsel[(bef*8+jo)*4096 + rowA + c_l*8 .. +7]
    // rev band (c_l, cj_l), chunk io: rsel[(befr*8+io)*4096 + rowB + cj_l*8 .. +7]
    // invalid chunks (same class / t >= NNEGS / non-offDiag rev) -> 0xFF
    unsigned char* RF = (unsigned char*)(smc + SM_RF);
    unsigned char* RR = (unsigned char*)(smc + SM_RR);
    #pragma unroll
    for (int ss = 0; ss < 4; ss++) {
        int cid = tid + ss * 512;                 // 0..2047
        int c_l = cid >> 7, cj_l = (cid >> 3) & 15, jo = cid & 7;
        int c = by * 16 + c_l, cj = bx * 16 + cj_l;
        int dd = abs(c - cj);
        int bef = max(0, c - dd) + max(0, (NCLS - 1) - c - dd)
                + ((cj > c && c >= dd) ? 1 : 0);
        int t = bef * 8 + jo;
        uint2 v = make_uint2(0xFFFFFFFFu, 0xFFFFFFFFu);
        if (c != cj && t < NNEGS)
            v = *(const uint2*)&g_rsel[(unsigned)t * NROWS + (unsigned)(rowA + c_l * 8)];
        *(uint2*)&RF[cid * 8] = v;

        int befr = max(0, cj - dd) + max(0, (NCLS - 1) - cj - dd)
                 + ((c > cj && cj >= dd) ? 1 : 0);
        int tr = befr * 8 + jo;                   // jo plays the role of io
        uint2 vr = make_uint2(0xFFFFFFFFu, 0xFFFFFFFFu);
        if (offDiag && tr < NNEGS)
            vr = *(const uint2*)&g_rsel[(unsigned)tr * NROWS + (unsigned)(rowB + cj_l * 8)];
        *(uint2*)&RR[cid * 8] = vr;
    }
    __syncthreads();

    // ---------------- fully-unrolled epilogue ----------------
    const float MC = MARGINF - 1.0f;
    float lsum = 0.0f;
    #pragma unroll
    for (int mr = 0; mr < 4; mr++) {
        int mt = mr >> 1, rh = mr & 1;
        int c_l = wr * 4 + mt * 2 + rh;
        int il = c_l * 8 + g;
        const float* dpi = &Dp[il * 9];
        #pragma unroll
        for (int nt = 0; nt < 4; nt++) {
            int cj_l = wc * 4 + nt;
            const unsigned char* bF = &RF[(c_l * 16 + cj_l) * 64];
            const unsigned char* bR = &RR[(c_l * 16 + cj_l) * 64];
            #pragma unroll
            for (int ch = 0; ch < 2; ch++) {
                int jq = 2 * t4 + ch;
                float s = acc[mt][nt][rh * 2 + ch];
                int rf = bF[jq * 8 + g];
                if (rf != 255)
                    lsum += fmaxf(dpi[rf] + s + MC, 0.0f);
                if (offDiag) {
                    int rr = bR[g * 8 + jq];
                    if (rr != 255) {
                        int jl = wc * 32 + nt * 8 + jq;
                        lsum += fmaxf(Dp[(128 + jl) * 9 + rr] + s + MC, 0.0f);
                    }
                }
            }
        }
    }

    // block reduction -> one atomicAdd per CTA (reuse Dp as scratch)
    #pragma unroll
    for (int o = 16; o; o >>= 1) lsum += __shfl_down_sync(0xffffffffu, lsum, o);
    __syncthreads();                       // everyone done reading Dp
    if ((tid & 31) == 0) Dp[tid >> 5] = lsum;
    __syncthreads();
    if (tid < 16) {
        float s2 = Dp[tid];
        #pragma unroll
        for (int o = 8; o; o >>= 1) s2 += __shfl_down_sync(0xffffu, s2, o);
        if (tid == 0) atomicAdd(out, s2);
    }
}

// ---------------------------------------------------------------------------
extern "C" void kernel_launch(void* const* d_in, const int* in_sizes, int n_in,
                              void* d_out, int out_size) {
    const float* samples = (const float*)d_in[0];
    float* out = (float*)d_out;

    cudaFuncSetAttribute(loss_kernel,
                         cudaFuncAttributeMaxDynamicSharedMemorySize, SM_TOTAL);
    prep_kernel<<<PREP_GRID, 256>>>(samples, out, out_size);
    loss_kernel<<<(TTILES * (TTILES + 1)) / 2, 512, SM_TOTAL>>>(out);
}